// round 16
// baseline (speedup 1.0000x reference)
#include <cuda_runtime.h>
#include <cuda_fp16.h>
#include <cstdint>

// ---------------- problem constants ----------------
#define N_IMG 32
#define HW_DIM 112
#define C_IN 128
#define C_OUT 256
#define PIX_PER_IMG (HW_DIM * HW_DIM)            // 12544
#define TILES_PER_IMG 49                          // 7x7 tiles of 16x16 px
#define NUM_CTAS (N_IMG * TILES_PER_IMG)          // 1568
#define NUM_CHUNKS 18                             // 9 taps * 2 halves
#define HALO 18
#define HALO_PIX (HALO * HALO)                    // 324
#define NTHREADS 288                              // 8 producer warps + 1 MMA warp

// ---------------- arch-feature guard ----------------
#if defined(__CUDA_ARCH_FEAT_SM103_ALL) || defined(__CUDA_ARCH_FEAT_SM100_ALL) || \
    defined(__CUDA_ARCH_SPECIFIC__) || defined(__CUDA_ARCH_FAMILY_SPECIFIC__)
#define HAS_TCGEN05 1
#else
#define HAS_TCGEN05 0
#endif

// ---------------- smem layout (bytes) ----------------
#define SM_TMEM   0
// fill mbarriers: 8,16 ; mma mbarriers: 32,40
#define SM_FMBAR  8
#define SM_MMBAR  32
#define SM_X      1024                 // halo: 324 px * 256 B = 82944 -> 83968
#define SM_A      83968                // A stages: 2 x 32768 -> 149504
#define A_STAGE_B 32768
#define A_TILE_B  16384
#define SM_B      149504               // B stages: 2 x 32768 -> 215040
#define B_STAGE_B 32768
#define SM_BIAS   215040               // 256 floats
#define SM_TOTAL  216064
#define SM_TBUF   SM_A                 // epilogue: 8 warps x 4096 B (reuses A)

// scratch (device global: allocation-free scratch per harness rules)
__device__ __half Wq_g[NUM_CHUNKS * C_OUT * 64];              // 576 KB

// ---------------- ptx helpers ----------------
__device__ __forceinline__ uint32_t smem_u32(const void* p) {
    uint32_t a;
    asm("{ .reg .u64 t; cvta.to.shared.u64 t, %1; cvt.u32.u64 %0, t; }"
        : "=r"(a) : "l"(p));
    return a;
}

__device__ __forceinline__ bool elect_one() {
    uint32_t pred;
    asm volatile(
        "{\n\t.reg .pred p;\n\telect.sync _|p, 0xFFFFFFFF;\n\t"
        "selp.b32 %0, 1, 0, p;\n\t}" : "=r"(pred));
    return pred != 0;
}

#define SW128(off) ((off) ^ (((off) >> 3) & 0x70))

__device__ __forceinline__ uint64_t make_desc_sw128(uint32_t addr) {
    uint64_t d = ((uint64_t)2 << 61) | ((uint64_t)1 << 46) |
                 ((uint64_t)64 << 32) | ((uint64_t)1 << 16);
    d |= (uint64_t)((addr >> 4) & 0x3FFF);
    return d;
}

__device__ __forceinline__ void cp_async16(uint32_t smem_addr, const void* gptr) {
    asm volatile("cp.async.cg.shared.global [%0], [%1], 16;"
                 :: "r"(smem_addr), "l"(gptr) : "memory");
}
// async arrival on mbar when this thread's prior cp.asyncs complete (.noinc:
// counts against init() expected count)
#define CP_ASYNC_MBAR_ARRIVE(mbar) \
    asm volatile("cp.async.mbarrier.arrive.noinc.shared::cta.b64 [%0];" \
                 :: "r"((uint32_t)(mbar)) : "memory")
#define MBARRIER_ARRIVE(mbar) \
    asm volatile("mbarrier.arrive.shared::cta.b64 _, [%0];" \
                 :: "r"((uint32_t)(mbar)) : "memory")

// shared-space 128-bit ops (explicit state space)
__device__ __forceinline__ void lds128(uint32_t addr, uint32_t& r0, uint32_t& r1,
                                       uint32_t& r2, uint32_t& r3) {
    asm volatile("ld.shared.v4.b32 {%0, %1, %2, %3}, [%4];"
                 : "=r"(r0), "=r"(r1), "=r"(r2), "=r"(r3) : "r"(addr));
}
__device__ __forceinline__ void sts128(uint32_t addr, uint32_t r0, uint32_t r1,
                                       uint32_t r2, uint32_t r3) {
    asm volatile("st.shared.v4.b32 [%0], {%1, %2, %3, %4};"
                 :: "r"(addr), "r"(r0), "r"(r1), "r"(r2), "r"(r3) : "memory");
}

#if HAS_TCGEN05

#define TCGEN05_ALLOC(smem_addr, nCols) \
    asm volatile("tcgen05.alloc.cta_group::1.sync.aligned.shared::cta.b32 [%0], %1;" \
                 :: "r"((uint32_t)(smem_addr)), "r"((uint32_t)(nCols)) : "memory")
#define TCGEN05_DEALLOC(tmem_addr, nCols) \
    asm volatile("tcgen05.dealloc.cta_group::1.sync.aligned.b32 %0, %1;" \
                 :: "r"(tmem_addr), "r"((uint32_t)(nCols)))
#define TCGEN05_RELINQUISH() \
    asm volatile("tcgen05.relinquish_alloc_permit.cta_group::1.sync.aligned;")
#define TCGEN05_COMMIT(mbar) \
    asm volatile("tcgen05.commit.cta_group::1.mbarrier::arrive::one.shared::cluster.b64 [%0];" \
                 :: "r"((uint32_t)(mbar)) : "memory")
#define TCGEN05_FENCE_AFTER() \
    asm volatile("tcgen05.fence::after_thread_sync;" ::: "memory")
#define TCGEN05_WAIT_LD() \
    asm volatile("tcgen05.wait::ld.sync.aligned;" ::: "memory")

#define TCGEN05_LD_32X32B_X32(r, tmem_addr) \
    asm volatile( \
        "tcgen05.ld.sync.aligned.32x32b.x32.b32 " \
        "{%0, %1, %2, %3, %4, %5, %6, %7, " \
        " %8, %9, %10, %11, %12, %13, %14, %15, " \
        " %16, %17, %18, %19, %20, %21, %22, %23, " \
        " %24, %25, %26, %27, %28, %29, %30, %31}, [%32];" \
        : "=r"((r)[0]),  "=r"((r)[1]),  "=r"((r)[2]),  "=r"((r)[3]), \
          "=r"((r)[4]),  "=r"((r)[5]),  "=r"((r)[6]),  "=r"((r)[7]), \
          "=r"((r)[8]),  "=r"((r)[9]),  "=r"((r)[10]), "=r"((r)[11]), \
          "=r"((r)[12]), "=r"((r)[13]), "=r"((r)[14]), "=r"((r)[15]), \
          "=r"((r)[16]), "=r"((r)[17]), "=r"((r)[18]), "=r"((r)[19]), \
          "=r"((r)[20]), "=r"((r)[21]), "=r"((r)[22]), "=r"((r)[23]), \
          "=r"((r)[24]), "=r"((r)[25]), "=r"((r)[26]), "=r"((r)[27]), \
          "=r"((r)[28]), "=r"((r)[29]), "=r"((r)[30]), "=r"((r)[31]) \
        : "r"(tmem_addr))

__device__ __forceinline__ void mma_f16_ss(uint32_t d_tmem, uint64_t a_desc,
                                           uint64_t b_desc, uint32_t idesc,
                                           uint32_t enable_d) {
    asm volatile(
        "{\n\t.reg .pred p;\n\t"
        "setp.ne.u32 p, %4, 0;\n\t"
        "tcgen05.mma.cta_group::1.kind::f16 [%0], %1, %2, %3, p;\n\t}"
        :: "r"(d_tmem), "l"(a_desc), "l"(b_desc), "r"(idesc), "r"(enable_d)
        : "memory");
}

#else  // portable-pass stubs (never executed on GB300)

#define TCGEN05_ALLOC(smem_addr, nCols)      do {} while (0)
#define TCGEN05_DEALLOC(tmem_addr, nCols)    do {} while (0)
#define TCGEN05_RELINQUISH()                 do {} while (0)
#define TCGEN05_COMMIT(mbar)                 do {} while (0)
#define TCGEN05_FENCE_AFTER()                do {} while (0)
#define TCGEN05_WAIT_LD()                    do {} while (0)
#define TCGEN05_LD_32X32B_X32(r, tmem_addr) \
    do { _Pragma("unroll") for (int _i = 0; _i < 32; _i++) (r)[_i] = 0u; } while (0)

__device__ __forceinline__ void mma_f16_ss(uint32_t, uint64_t, uint64_t,
                                           uint32_t, uint32_t) {}

#endif  // HAS_TCGEN05

#define FENCE_PROXY_ASYNC_SHARED() \
    asm volatile("fence.proxy.async.shared::cta;" ::: "memory")

#define MBARRIER_INIT(mbar, count) \
    asm volatile("mbarrier.init.shared.b64 [%0], %1;" \
                 :: "r"((uint32_t)(mbar)), "r"((uint32_t)(count)) : "memory")

#define MBARRIER_WAIT_PARITY(mbar_addr, phase_parity) do { \
    uint32_t _mbar = (uint32_t)(mbar_addr); \
    uint32_t _parity = (uint32_t)(phase_parity); \
    uint32_t _done; \
    asm volatile( \
        "{\n\t.reg .pred p;\n\t" \
        "mbarrier.try_wait.parity.acquire.cta.shared::cta.b64 p, [%1], %2;\n\t" \
        "selp.b32 %0, 1, 0, p;\n\t}" \
        : "=r"(_done) : "r"(_mbar), "r"(_parity) : "memory"); \
    if (!_done) { \
        asm volatile( \
            "{\n\t.reg .pred P1;\n\t" \
            "WAIT_LOOP_%=:\n\t" \
            "mbarrier.try_wait.parity.acquire.cta.shared::cta.b64 P1, [%0], %1, 0x989680;\n\t" \
            "@P1 bra.uni WAIT_DONE_%=;\n\t" \
            "bra.uni WAIT_LOOP_%=;\n\t" \
            "WAIT_DONE_%=:\n\t}" \
            :: "r"(_mbar), "r"(_parity) : "memory"); \
    } \
} while (0)

// idesc: F32 accum (1<<4), FP16 a/b, N=256 -> (32<<17), M=128 -> (8<<24)
#define MMA_IDESC 0x8400010u

// ---------------- prep kernel: binarize + pack W ----------------
// packing: chunk = tap*2 + half; Wq_g[chunk][co][64]
__global__ void quant_w_kernel(const float* __restrict__ W) {
    int o = blockIdx.x * 256 + threadIdx.x;
    if (o < NUM_CHUNKS * C_OUT * 64) {
        int col = o & 63;
        int co = (o >> 6) & 255;
        int tc = o >> 14;
        int tap = tc >> 1, ch = tc & 1;
        int ci = ch * 64 + col;
        float w = W[(tap * C_IN + ci) * C_OUT + co];
        Wq_g[o] = __float2half(w > 0.f ? 1.f : (w < 0.f ? -1.f : 0.f));
    }
}

// ---------------- main fused conv kernel ----------------
// 16x16-px tile per CTA; fp32 halo loaded once (inline fp16 convert);
// producers (warps 0-7) build A tiles SMEM->SMEM + stream B via cp.async;
// warp 8 = dedicated MMA warp; 2-stage sync-free mbarrier pipeline.
__global__ void __launch_bounds__(NTHREADS, 1)
bconv_main_kernel(const float* __restrict__ x, const float* __restrict__ bias,
                  float* __restrict__ out) {
    extern __shared__ char smem[];
    uint32_t smem_base = smem_u32(smem);
    int tid = threadIdx.x;
    int wid = tid >> 5, lid = tid & 31;

    if (wid == 0) {
        TCGEN05_ALLOC(smem_base + SM_TMEM, 512);
        TCGEN05_RELINQUISH();
    }
    if (tid == 0) {
        #pragma unroll
        for (int s = 0; s < 2; s++) {
            // fill: 256 regular (A-build) + 256 cp.async (B) arrivals per phase
            MBARRIER_INIT(smem_base + SM_FMBAR + s * 8, 512);
            MBARRIER_INIT(smem_base + SM_MMBAR + s * 8, 1);
        }
    }
    __syncthreads();
    uint32_t tmem_base;
    asm volatile("ld.shared.b32 %0, [%1];" : "=r"(tmem_base)
                 : "r"(smem_base + SM_TMEM));

    // tile coordinates
    int img = blockIdx.x / TILES_PER_IMG;
    int t49 = blockIdx.x % TILES_PER_IMG;
    int ty0 = (t49 / 7) * 16, tx0 = (t49 % 7) * 16;
    size_t img_px = (size_t)img * PIX_PER_IMG;

    bool producer = (tid < 256);

    // ---- halo: 18x18 px * 128 ci fp32 -> fp16 SMEM (once, producers) ----
    if (producer) {
        const float* xg = x + img_px * C_IN;
        for (int idx = tid; idx < HALO_PIX * 32; idx += 256) {
            int pix = idx >> 5, c4 = idx & 31;
            int py = ty0 - 1 + pix / HALO;
            int px = tx0 - 1 + pix % HALO;
            uint2 u = make_uint2(0u, 0u);
            if ((unsigned)py < (unsigned)HW_DIM && (unsigned)px < (unsigned)HW_DIM) {
                float4 v = *reinterpret_cast<const float4*>(
                    xg + ((size_t)py * HW_DIM + px) * C_IN + c4 * 4);
                __half2 h0 = __floats2half2_rn(v.x, v.y);
                __half2 h1 = __floats2half2_rn(v.z, v.w);
                u.x = *reinterpret_cast<uint32_t*>(&h0);
                u.y = *reinterpret_cast<uint32_t*>(&h1);
            }
            *reinterpret_cast<uint2*>(smem + SM_X + pix * 256 + c4 * 8) = u;
        }
    }
    __syncthreads();                              // halo visible to producers

    // ---- per-producer precomputed addresses ----
    int seg = tid & 7;                            // 16B segment in 128B row
    int prow = (tid & 255) >> 3;                  // base row (step 32)
    uint32_t ldsA[8], stsA[8], stsB[8];
    #pragma unroll
    for (int t = 0; t < 2; t++) {
        #pragma unroll
        for (int i = 0; i < 4; i++) {
            int r = prow + i * 32;
            int lp = t * 128 + r;
            int oy = lp >> 4, ox = lp & 15;
            ldsA[t * 4 + i] = smem_base + SM_X +
                              (uint32_t)(oy * HALO + ox) * 256 + seg * 16;
            stsA[t * 4 + i] = smem_base + SM_A + t * A_TILE_B +
                              SW128((uint32_t)r * 128 + seg * 16);
        }
    }
    #pragma unroll
    for (int i = 0; i < 8; i++) {
        int item = (tid & 255) + i * 256;
        stsB[i] = smem_base + SM_B +
                  SW128((uint32_t)(item >> 3) * 128 + (item & 7) * 16);
    }

    // fill stage s with chunk c: A-build (SMEM->SMEM) + B (cp.async), publish
    auto fill_stage = [&](int c, int s) {
        int tap = c >> 1, half_k = c & 1;
        uint32_t ldelta = (uint32_t)((tap / 3) * HALO + (tap % 3)) * 256 +
                          half_k * 128;
        uint32_t aoff = (uint32_t)s * A_STAGE_B;
        #pragma unroll
        for (int k = 0; k < 8; k++) {
            uint32_t r0, r1, r2, r3;
            lds128(ldsA[k] + ldelta, r0, r1, r2, r3);
            sts128(stsA[k] + aoff, r0, r1, r2, r3);
        }
        const __half* wsrc = Wq_g + (size_t)c * (C_OUT * 64) + (tid & 255) * 8;
        uint32_t boff = (uint32_t)s * B_STAGE_B;
        #pragma unroll
        for (int i = 0; i < 8; i++)
            cp_async16(stsB[i] + boff, wsrc + i * 2048);
        FENCE_PROXY_ASYNC_SHARED();               // A stores -> async proxy
        MBARRIER_ARRIVE(smem_base + SM_FMBAR + s * 8);
        CP_ASYNC_MBAR_ARRIVE(smem_base + SM_FMBAR + s * 8);
    };

    // prologue: fill stages 0 and 1
    if (producer) {
        fill_stage(0, 0);
        fill_stage(1, 1);
    }

    #pragma unroll 1
    for (int c = 0; c < NUM_CHUNKS; c++) {
        int s = c & 1;
        int par = (c >> 1) & 1;

        if (wid == 8) {
            MBARRIER_WAIT_PARITY(smem_base + SM_FMBAR + s * 8, par);
            if (elect_one()) {
                FENCE_PROXY_ASYNC_SHARED();
                uint32_t ab = smem_base + SM_A + s * A_STAGE_B;
                uint64_t a0 = make_desc_sw128(ab);
                uint64_t a1 = make_desc_sw128(ab + A_TILE_B);
                uint64_t bd = make_desc_sw128(smem_base + SM_B + s * B_STAGE_B);
                uint32_t en = (c > 0);
                #pragma unroll
                for (int q = 0; q < 4; q++)
                    mma_f16_ss(tmem_base, a0 + q * 2, bd + q * 2,
                               MMA_IDESC, en | (q > 0));
                #pragma unroll
                for (int q = 0; q < 4; q++)
                    mma_f16_ss(tmem_base + 256, a1 + q * 2, bd + q * 2,
                               MMA_IDESC, en | (q > 0));
                TCGEN05_COMMIT(smem_base + SM_MMBAR + s * 8);
            }
        } else if (producer && c + 2 < NUM_CHUNKS) {
            // stage s reusable once MMA(c) completed
            MBARRIER_WAIT_PARITY(smem_base + SM_MMBAR + s * 8, par);
            fill_stage(c + 2, s);
        }
    }

    // drain: commit(17) covers all prior MMAs (mbar 1, 9th phase -> parity 0)
    MBARRIER_WAIT_PARITY(smem_base + SM_MMBAR + 8, 0);
    TCGEN05_FENCE_AFTER();

    // ---- epilogue: warp-private transpose (warps 0-7), no block barriers ----
    float* bsm = reinterpret_cast<float*>(smem + SM_BIAS);
    if (producer) bsm[tid] = bias[tid];
    __syncthreads();

    if (wid < 8) {
        int wg = wid >> 2;                        // tile half (0/1)
        int sp = wid & 3;                         // subpartition
        uint32_t tbw = smem_base + SM_TBUF + (uint32_t)wid * 4096;
        int lp_base = wg * 128 + sp * 32;         // local pixel of this warp's row 0

        #pragma unroll 1
        for (int cb = 0; cb < 8; cb++) {
            uint32_t regs[32];
            TCGEN05_LD_32X32B_X32(regs, tmem_base + wg * 256 + cb * 32);
            TCGEN05_WAIT_LD();
            #pragma unroll
            for (int k = 0; k < 8; k++) {
                uint32_t a0 = __float_as_uint(__uint_as_float(regs[4 * k + 0]) + bsm[cb * 32 + 4 * k + 0]);
                uint32_t a1 = __float_as_uint(__uint_as_float(regs[4 * k + 1]) + bsm[cb * 32 + 4 * k + 1]);
                uint32_t a2 = __float_as_uint(__uint_as_float(regs[4 * k + 2]) + bsm[cb * 32 + 4 * k + 2]);
                uint32_t a3 = __float_as_uint(__uint_as_float(regs[4 * k + 3]) + bsm[cb * 32 + 4 * k + 3]);
                sts128(tbw + (uint32_t)lid * 128 + (((k + lid) & 7) << 4), a0, a1, a2, a3);
            }
            __syncwarp();
            #pragma unroll
            for (int k = 0; k < 8; k++) {
                int p = k * 4 + (lid >> 3);
                int cc = lid & 7;
                uint32_t r0, r1, r2, r3;
                lds128(tbw + (uint32_t)p * 128 + (((cc + p) & 7) << 4), r0, r1, r2, r3);
                float4 v = make_float4(__uint_as_float(r0), __uint_as_float(r1),
                                       __uint_as_float(r2), __uint_as_float(r3));
                int lp = lp_base + p;
                int oy = lp >> 4, ox = lp & 15;
                size_t gp = img_px + (size_t)(ty0 + oy) * HW_DIM + (tx0 + ox);
                *reinterpret_cast<float4*>(
                    out + gp * C_OUT + cb * 32 + cc * 4) = v;
            }
            __syncwarp();
        }
    }

    __syncthreads();                              // no warp may still touch TMEM
    if (wid == 0) {
        TCGEN05_DEALLOC(tmem_base, 512);
    }
}

// ---------------- launch ----------------
extern "C" void kernel_launch(void* const* d_in, const int* in_sizes, int n_in,
                              void* d_out, int out_size) {
    const float* x = (const float*)d_in[0];
    const float* W = (const float*)d_in[1];
    const float* b = (const float*)d_in[2];
    float* out = (float*)d_out;

    cudaFuncSetAttribute(bconv_main_kernel,
                         cudaFuncAttributeMaxDynamicSharedMemorySize, SM_TOTAL);

    quant_w_kernel<<<(NUM_CHUNKS * C_OUT * 64) / 256, 256>>>(W);
    bconv_main_kernel<<<NUM_CTAS, NTHREADS, SM_TOTAL>>>(x, b, out);
}

// round 17
// speedup vs baseline: 1.1582x; 1.1582x over previous
#include <cuda_runtime.h>
#include <cuda_fp16.h>
#include <cstdint>

// ---------------- problem constants ----------------
#define N_IMG 32
#define HW_DIM 112
#define C_IN 128
#define C_OUT 256
#define PIX_PER_IMG (HW_DIM * HW_DIM)            // 12544
#define TOT_PIX (N_IMG * PIX_PER_IMG)            // 401408
#define NUM_TILES (TOT_PIX / 128)                // 3136 CTAs, 1 M-tile each
#define NUM_CHUNKS 18                             // 9 taps * 2 halves
#define NTHREADS 288                              // 8 producer warps + 1 MMA warp

// ---------------- arch-feature guard ----------------
#if defined(__CUDA_ARCH_FEAT_SM103_ALL) || defined(__CUDA_ARCH_FEAT_SM100_ALL) || \
    defined(__CUDA_ARCH_SPECIFIC__) || defined(__CUDA_ARCH_FAMILY_SPECIFIC__)
#define HAS_TCGEN05 1
#else
#define HAS_TCGEN05 0
#endif

// ---------------- smem layout (bytes) ----------------
#define SM_TMEM   0
// fill mbarriers: 8,16 ; mma mbarriers: 32,40
#define SM_FMBAR  8
#define SM_MMBAR  32
#define SM_STAGE  1024                // 2 stages x 49152
#define STAGE_BYTES 49152             // A 16K | B 32K
#define A_TILE_B  16384
#define B_OFF     16384
#define SM_BIAS   (SM_STAGE + 2 * STAGE_BYTES)          // 99328
#define SM_TOTAL  (SM_BIAS + 1024)                      // 100352 (x2 CTAs = 196K/SM)
#define SM_TBUF   SM_STAGE            // epilogue: 8 warps x 4096 B (reuses stage0)

// scratch (device globals: allocation-free scratch per harness rules)
__device__ __half Xh_g[(size_t)TOT_PIX * C_IN];               // ~103 MB
__device__ __half Wq_g[NUM_CHUNKS * C_OUT * 64];              // 576 KB

// ---------------- ptx helpers ----------------
__device__ __forceinline__ uint32_t smem_u32(const void* p) {
    uint32_t a;
    asm("{ .reg .u64 t; cvta.to.shared.u64 t, %1; cvt.u32.u64 %0, t; }"
        : "=r"(a) : "l"(p));
    return a;
}

__device__ __forceinline__ bool elect_one() {
    uint32_t pred;
    asm volatile(
        "{\n\t.reg .pred p;\n\telect.sync _|p, 0xFFFFFFFF;\n\t"
        "selp.b32 %0, 1, 0, p;\n\t}" : "=r"(pred));
    return pred != 0;
}

#define SW128(off) ((off) ^ (((off) >> 3) & 0x70))

__device__ __forceinline__ uint64_t make_desc_sw128(uint32_t addr) {
    uint64_t d = ((uint64_t)2 << 61) | ((uint64_t)1 << 46) |
                 ((uint64_t)64 << 32) | ((uint64_t)1 << 16);
    d |= (uint64_t)((addr >> 4) & 0x3FFF);
    return d;
}

// cp.async 16B with zero-fill when !ok (src_size = 0 reads nothing)
__device__ __forceinline__ void cp_async16z(uint32_t smem_addr, const void* gptr,
                                            bool ok) {
    int sz = ok ? 16 : 0;
    asm volatile("cp.async.cg.shared.global [%0], [%1], 16, %2;"
                 :: "r"(smem_addr), "l"(gptr), "r"(sz) : "memory");
}
__device__ __forceinline__ void cp_async16(uint32_t smem_addr, const void* gptr) {
    asm volatile("cp.async.cg.shared.global [%0], [%1], 16;"
                 :: "r"(smem_addr), "l"(gptr) : "memory");
}
// async arrival on mbar when this thread's prior cp.asyncs complete (.noinc:
// counts against init() expected count)
#define CP_ASYNC_MBAR_ARRIVE(mbar) \
    asm volatile("cp.async.mbarrier.arrive.noinc.shared::cta.b64 [%0];" \
                 :: "r"((uint32_t)(mbar)) : "memory")

// shared-space 128-bit ops (explicit state space)
__device__ __forceinline__ void lds128(uint32_t addr, uint32_t& r0, uint32_t& r1,
                                       uint32_t& r2, uint32_t& r3) {
    asm volatile("ld.shared.v4.b32 {%0, %1, %2, %3}, [%4];"
                 : "=r"(r0), "=r"(r1), "=r"(r2), "=r"(r3) : "r"(addr));
}
__device__ __forceinline__ void sts128(uint32_t addr, uint32_t r0, uint32_t r1,
                                       uint32_t r2, uint32_t r3) {
    asm volatile("st.shared.v4.b32 [%0], {%1, %2, %3, %4};"
                 :: "r"(addr), "r"(r0), "r"(r1), "r"(r2), "r"(r3) : "memory");
}

#if HAS_TCGEN05

#define TCGEN05_ALLOC(smem_addr, nCols) \
    asm volatile("tcgen05.alloc.cta_group::1.sync.aligned.shared::cta.b32 [%0], %1;" \
                 :: "r"((uint32_t)(smem_addr)), "r"((uint32_t)(nCols)) : "memory")
#define TCGEN05_DEALLOC(tmem_addr, nCols) \
    asm volatile("tcgen05.dealloc.cta_group::1.sync.aligned.b32 %0, %1;" \
                 :: "r"(tmem_addr), "r"((uint32_t)(nCols)))
#define TCGEN05_RELINQUISH() \
    asm volatile("tcgen05.relinquish_alloc_permit.cta_group::1.sync.aligned;")
#define TCGEN05_COMMIT(mbar) \
    asm volatile("tcgen05.commit.cta_group::1.mbarrier::arrive::one.shared::cluster.b64 [%0];" \
                 :: "r"((uint32_t)(mbar)) : "memory")
#define TCGEN05_FENCE_AFTER() \
    asm volatile("tcgen05.fence::after_thread_sync;" ::: "memory")
#define TCGEN05_WAIT_LD() \
    asm volatile("tcgen05.wait::ld.sync.aligned;" ::: "memory")

#define TCGEN05_LD_32X32B_X32(r, tmem_addr) \
    asm volatile( \
        "tcgen05.ld.sync.aligned.32x32b.x32.b32 " \
        "{%0, %1, %2, %3, %4, %5, %6, %7, " \
        " %8, %9, %10, %11, %12, %13, %14, %15, " \
        " %16, %17, %18, %19, %20, %21, %22, %23, " \
        " %24, %25, %26, %27, %28, %29, %30, %31}, [%32];" \
        : "=r"((r)[0]),  "=r"((r)[1]),  "=r"((r)[2]),  "=r"((r)[3]), \
          "=r"((r)[4]),  "=r"((r)[5]),  "=r"((r)[6]),  "=r"((r)[7]), \
          "=r"((r)[8]),  "=r"((r)[9]),  "=r"((r)[10]), "=r"((r)[11]), \
          "=r"((r)[12]), "=r"((r)[13]), "=r"((r)[14]), "=r"((r)[15]), \
          "=r"((r)[16]), "=r"((r)[17]), "=r"((r)[18]), "=r"((r)[19]), \
          "=r"((r)[20]), "=r"((r)[21]), "=r"((r)[22]), "=r"((r)[23]), \
          "=r"((r)[24]), "=r"((r)[25]), "=r"((r)[26]), "=r"((r)[27]), \
          "=r"((r)[28]), "=r"((r)[29]), "=r"((r)[30]), "=r"((r)[31]) \
        : "r"(tmem_addr))

__device__ __forceinline__ void mma_f16_ss(uint32_t d_tmem, uint64_t a_desc,
                                           uint64_t b_desc, uint32_t idesc,
                                           uint32_t enable_d) {
    asm volatile(
        "{\n\t.reg .pred p;\n\t"
        "setp.ne.u32 p, %4, 0;\n\t"
        "tcgen05.mma.cta_group::1.kind::f16 [%0], %1, %2, %3, p;\n\t}"
        :: "r"(d_tmem), "l"(a_desc), "l"(b_desc), "r"(idesc), "r"(enable_d)
        : "memory");
}

#else  // portable-pass stubs (never executed on GB300)

#define TCGEN05_ALLOC(smem_addr, nCols)      do {} while (0)
#define TCGEN05_DEALLOC(tmem_addr, nCols)    do {} while (0)
#define TCGEN05_RELINQUISH()                 do {} while (0)
#define TCGEN05_COMMIT(mbar)                 do {} while (0)
#define TCGEN05_FENCE_AFTER()                do {} while (0)
#define TCGEN05_WAIT_LD()                    do {} while (0)
#define TCGEN05_LD_32X32B_X32(r, tmem_addr) \
    do { _Pragma("unroll") for (int _i = 0; _i < 32; _i++) (r)[_i] = 0u; } while (0)

__device__ __forceinline__ void mma_f16_ss(uint32_t, uint64_t, uint64_t,
                                           uint32_t, uint32_t) {}

#endif  // HAS_TCGEN05

#define FENCE_PROXY_ASYNC_SHARED() \
    asm volatile("fence.proxy.async.shared::cta;" ::: "memory")

#define MBARRIER_INIT(mbar, count) \
    asm volatile("mbarrier.init.shared.b64 [%0], %1;" \
                 :: "r"((uint32_t)(mbar)), "r"((uint32_t)(count)) : "memory")

#define MBARRIER_WAIT_PARITY(mbar_addr, phase_parity) do { \
    uint32_t _mbar = (uint32_t)(mbar_addr); \
    uint32_t _parity = (uint32_t)(phase_parity); \
    uint32_t _done; \
    asm volatile( \
        "{\n\t.reg .pred p;\n\t" \
        "mbarrier.try_wait.parity.acquire.cta.shared::cta.b64 p, [%1], %2;\n\t" \
        "selp.b32 %0, 1, 0, p;\n\t}" \
        : "=r"(_done) : "r"(_mbar), "r"(_parity) : "memory"); \
    if (!_done) { \
        asm volatile( \
            "{\n\t.reg .pred P1;\n\t" \
            "WAIT_LOOP_%=:\n\t" \
            "mbarrier.try_wait.parity.acquire.cta.shared::cta.b64 P1, [%0], %1, 0x989680;\n\t" \
            "@P1 bra.uni WAIT_DONE_%=;\n\t" \
            "bra.uni WAIT_LOOP_%=;\n\t" \
            "WAIT_DONE_%=:\n\t}" \
            :: "r"(_mbar), "r"(_parity) : "memory"); \
    } \
} while (0)

// idesc: F32 accum (1<<4), FP16 a/b, N=256 -> (32<<17), M=128 -> (8<<24)
#define MMA_IDESC 0x8400010u

// ---------------- prep kernels ----------------
__global__ void convert_x_kernel(const float4* __restrict__ x, int n4) {
    int i = blockIdx.x * 256 + threadIdx.x;
    if (i < n4) {
        float4 v = x[i];
        __half2 h0 = __floats2half2_rn(v.x, v.y);
        __half2 h1 = __floats2half2_rn(v.z, v.w);
        uint2 u;
        u.x = *reinterpret_cast<uint32_t*>(&h0);
        u.y = *reinterpret_cast<uint32_t*>(&h1);
        reinterpret_cast<uint2*>(Xh_g)[i] = u;
    }
}

__global__ void quant_w_kernel(const float* __restrict__ W) {
    int o = blockIdx.x * 256 + threadIdx.x;
    if (o < NUM_CHUNKS * C_OUT * 64) {
        int col = o & 63;
        int co = (o >> 6) & 255;
        int tc = o >> 14;                       // chunk = tap*2 + half
        int tap = tc >> 1, ch = tc & 1;
        int ci = ch * 64 + col;
        float w = W[(tap * C_IN + ci) * C_OUT + co];
        Wq_g[o] = __float2half(w > 0.f ? 1.f : (w < 0.f ? -1.f : 0.f));
    }
}

// ---------------- main implicit-GEMM conv kernel ----------------
// ONE 128-px M-tile per CTA (TMEM 256 cols -> 2 CTAs/SM); warps 0-7 producers
// (pure cp.async fills), warp 8 dedicated MMA warp; 2-stage mbarrier pipeline;
// warp-private epilogue (each warp: 1 subpartition x 4 col-blocks).
__global__ void __launch_bounds__(NTHREADS, 2)
bconv_main_kernel(const float* __restrict__ bias, float* __restrict__ out) {
    extern __shared__ char smem[];
    uint32_t smem_base = smem_u32(smem);
    int tid = threadIdx.x;
    int wid = tid >> 5, lid = tid & 31;

    if (wid == 0) {
        TCGEN05_ALLOC(smem_base + SM_TMEM, 256);
        TCGEN05_RELINQUISH();
    }
    if (tid == 0) {
        #pragma unroll
        for (int s = 0; s < 2; s++) {
            MBARRIER_INIT(smem_base + SM_FMBAR + s * 8, 256);   // producer threads
            MBARRIER_INIT(smem_base + SM_MMBAR + s * 8, 1);     // tcgen05 commit
        }
    }
    __syncthreads();
    uint32_t tmem_base;
    asm volatile("ld.shared.b32 %0, [%1];" : "=r"(tmem_base)
                 : "r"(smem_base + SM_TMEM));

    int pix_base = blockIdx.x * 128;

    // per-producer A-fill coordinates: 4 row-steps
    int hA[4], wA[4];
    size_t rowA[4];
    int seg = tid & 7;                            // 16B segment in 128B row
    int prow = (tid & 255) >> 3;                  // base row (step 32)
    #pragma unroll
    for (int i = 0; i < 4; i++) {
        int gp = pix_base + prow + i * 32;
        int n = gp / PIX_PER_IMG;
        int r = gp % PIX_PER_IMG;
        hA[i] = r / HW_DIM;
        wA[i] = r % HW_DIM;
        rowA[i] = (size_t)n * PIX_PER_IMG * C_IN;
    }

    // async fill of one chunk-stage (256 producer threads, 12 cp.async each)
    auto fill_stage = [&](int c, int s) {
        int tap = c >> 1, half_k = c & 1;
        int kh = tap / 3 - 1, kw = tap % 3 - 1;
        uint32_t sb = smem_base + SM_STAGE + s * STAGE_BYTES;
        #pragma unroll
        for (int i = 0; i < 4; i++) {
            int hh = hA[i] + kh, ww = wA[i] + kw;
            bool ok = ((unsigned)hh < (unsigned)HW_DIM) &&
                      ((unsigned)ww < (unsigned)HW_DIM);
            const __half* src = Xh_g + rowA[i] +
                ((size_t)(ok ? hh : 0) * HW_DIM + (ok ? ww : 0)) * C_IN +
                half_k * 64 + seg * 8;
            uint32_t off = (uint32_t)(prow + i * 32) * 128 + seg * 16;
            cp_async16z(sb + SW128(off), src, ok);
        }
        const __half* wsrc = Wq_g + (size_t)c * (C_OUT * 64);
        int base = tid & 255;
        #pragma unroll
        for (int i = 0; i < 8; i++) {
            int item = base + i * 256;            // 0..2047
            uint32_t off = (uint32_t)(item >> 3) * 128 + (item & 7) * 16;
            cp_async16(sb + B_OFF + SW128(off), wsrc + item * 8);
        }
        CP_ASYNC_MBAR_ARRIVE(smem_base + SM_FMBAR + s * 8);
    };

    bool producer = (tid < 256);

    // prologue: fill stages 0 and 1
    if (producer) {
        fill_stage(0, 0);
        fill_stage(1, 1);
    }

    #pragma unroll 1
    for (int c = 0; c < NUM_CHUNKS; c++) {
        int s = c & 1;
        int par = (c >> 1) & 1;

        if (wid == 8) {
            // MMA warp: wait fill(c), fence, issue, commit
            MBARRIER_WAIT_PARITY(smem_base + SM_FMBAR + s * 8, par);
            if (elect_one()) {
                FENCE_PROXY_ASYNC_SHARED();
                uint32_t sb = smem_base + SM_STAGE + s * STAGE_BYTES;
                uint64_t ad = make_desc_sw128(sb);
                uint64_t bd = make_desc_sw128(sb + B_OFF);
                uint32_t en = (c > 0);
                #pragma unroll
                for (int q = 0; q < 4; q++)
                    mma_f16_ss(tmem_base, ad + q * 2, bd + q * 2,
                               MMA_IDESC, en | (q > 0));
                TCGEN05_COMMIT(smem_base + SM_MMBAR + s * 8);
            }
        } else if (producer && c + 2 < NUM_CHUNKS) {
            // producers: stage s free once MMA(c) completed
            MBARRIER_WAIT_PARITY(smem_base + SM_MMBAR + s * 8, par);
            fill_stage(c + 2, s);
        }
    }

    // drain: commit(17) covers all prior MMAs (mbar 1, phase 8 -> parity 0)
    MBARRIER_WAIT_PARITY(smem_base + SM_MMBAR + 8, 0);
    TCGEN05_FENCE_AFTER();

    // ---- epilogue: 8 warps, each 1 subpartition x 4 col-blocks ----
    float* bsm = reinterpret_cast<float*>(smem + SM_BIAS);
    if (producer) bsm[tid] = bias[tid];
    __syncthreads();

    if (wid < 8) {
        int sp = wid & 3;                         // TMEM subpartition (rows)
        int cbh = wid >> 2;                       // col-block half (0/1)
        uint32_t tbw = smem_base + SM_TBUF + (uint32_t)wid * 4096;
        int prow_g = pix_base + sp * 32;

        #pragma unroll 1
        for (int j = 0; j < 4; j++) {
            int cb = cbh * 4 + j;
            uint32_t regs[32];
            TCGEN05_LD_32X32B_X32(regs, tmem_base + cb * 32);
            TCGEN05_WAIT_LD();
            #pragma unroll
            for (int k = 0; k < 8; k++) {
                uint32_t a0 = __float_as_uint(__uint_as_float(regs[4 * k + 0]) + bsm[cb * 32 + 4 * k + 0]);
                uint32_t a1 = __float_as_uint(__uint_as_float(regs[4 * k + 1]) + bsm[cb * 32 + 4 * k + 1]);
                uint32_t a2 = __float_as_uint(__uint_as_float(regs[4 * k + 2]) + bsm[cb * 32 + 4 * k + 2]);
                uint32_t a3 = __float_as_uint(__uint_as_float(regs[4 * k + 3]) + bsm[cb * 32 + 4 * k + 3]);
                sts128(tbw + (uint32_t)lid * 128 + (((k + lid) & 7) << 4), a0, a1, a2, a3);
            }
            __syncwarp();
            #pragma unroll
            for (int k = 0; k < 8; k++) {
                int p = k * 4 + (lid >> 3);
                int cc = lid & 7;
                uint32_t r0, r1, r2, r3;
                lds128(tbw + (uint32_t)p * 128 + (((cc + p) & 7) << 4), r0, r1, r2, r3);
                float4 v = make_float4(__uint_as_float(r0), __uint_as_float(r1),
                                       __uint_as_float(r2), __uint_as_float(r3));
                *reinterpret_cast<float4*>(
                    out + (size_t)(prow_g + p) * C_OUT + cb * 32 + cc * 4) = v;
            }
            __syncwarp();
        }
    }

    __syncthreads();                              // no warp may still touch TMEM
    if (wid == 0) {
        TCGEN05_DEALLOC(tmem_base, 256);
    }
}

// ---------------- launch ----------------
extern "C" void kernel_launch(void* const* d_in, const int* in_sizes, int n_in,
                              void* d_out, int out_size) {
    const float* x = (const float*)d_in[0];
    const float* W = (const float*)d_in[1];
    const float* b = (const float*)d_in[2];
    float* out = (float*)d_out;

    cudaFuncSetAttribute(bconv_main_kernel,
                         cudaFuncAttributeMaxDynamicSharedMemorySize, SM_TOTAL);

    int n4 = (TOT_PIX * C_IN) / 4;
    convert_x_kernel<<<n4 / 256, 256>>>(reinterpret_cast<const float4*>(x), n4);
    quant_w_kernel<<<(NUM_CHUNKS * C_OUT * 64) / 256, 256>>>(W);
    bconv_main_kernel<<<NUM_TILES, NTHREADS, SM_TOTAL>>>(b, out);
}